// round 4
// baseline (speedup 1.0000x reference)
#include <cuda_runtime.h>

// Problem constants
#define Nv    20000
#define Tt    32
#define Ee    640000
#define Cc    10
#define Kk    5
#define PADc  2
#define GSTAT 160
#define GOUT  160

// ---------------- static device scratch (no allocs allowed) ----------------
__device__ int   g_counts[Nv];
__device__ int   g_row[Nv + 1];
__device__ int   g_cursor[Nv];
__device__ int   g_adj[Ee];
__device__ float g_invdeg[Nv];
__device__ float g_xn[Nv * Tt];     // normalized x of current layer
__device__ float g_cm[Nv * Tt];     // per-node conv+max message
__device__ float g_x[Nv * Tt];      // layer output buffer
__device__ float g_part[GSTAT * 64];
__device__ float g_mean[Tt];        // alpha * mean (subtract term)
__device__ float g_invn[Tt];        // sqrt(N)/||x - alpha*mean||
__device__ float g_opart[GOUT * 3];

// ---------------- CSR build ----------------
__global__ __launch_bounds__(256) void zero_counts_k() {
    int i = blockIdx.x * blockDim.x + threadIdx.x;
    if (i < Nv) g_counts[i] = 0;
}

__global__ __launch_bounds__(256) void count_k(const int* __restrict__ ei) {
    int e = blockIdx.x * blockDim.x + threadIdx.x;
    if (e < Ee) atomicAdd(&g_counts[ei[Ee + e]], 1);
}

// single-block exclusive scan over 20000 counts (512 threads x 40 elems)
__global__ __launch_bounds__(512) void scan_k() {
    const int NTH = 512;
    const int CH = 40;  // 512*40 = 20480 >= Nv
    int tid = threadIdx.x;
    int base = tid * CH;
    int s = 0;
    for (int i = 0; i < CH; i++) {
        int idx = base + i;
        if (idx < Nv) s += g_counts[idx];
    }
    __shared__ int sh[NTH];
    sh[tid] = s;
    __syncthreads();
    for (int off = 1; off < NTH; off <<= 1) {
        int v = 0;
        if (tid >= off) v = sh[tid - off];
        __syncthreads();
        if (tid >= off) sh[tid] += v;
        __syncthreads();
    }
    int run = sh[tid] - s;  // exclusive prefix of this thread's chunk
    for (int i = 0; i < CH; i++) {
        int idx = base + i;
        if (idx < Nv) {
            int c = g_counts[idx];
            g_row[idx] = run;
            g_cursor[idx] = run;
            g_invdeg[idx] = 1.0f / (float)(c > 1 ? c : 1);
            run += c;
        }
    }
    if (tid == NTH - 1) g_row[Nv] = sh[NTH - 1];
}

__global__ __launch_bounds__(256) void scatter_k(const int* __restrict__ ei) {
    int e = blockIdx.x * blockDim.x + threadIdx.x;
    if (e < Ee) {
        int d = ei[Ee + e];
        int p = atomicAdd(&g_cursor[d], 1);
        g_adj[p] = ei[e];
    }
}

// ---------------- per-layer: column stats (deterministic 2-stage) ----------
// use_gx: 0 -> read from external x, 1 -> read from g_x
__global__ __launch_bounds__(256) void stats_k(const float* __restrict__ x, int use_gx) {
    const float* __restrict__ src = use_gx ? (const float*)g_x : x;
    int lane = threadIdx.x & 31;
    int w = threadIdx.x >> 5;  // 0..7
    int wg = blockIdx.x * 8 + w;
    float s = 0.f, q = 0.f;
    for (int n = wg; n < Nv; n += gridDim.x * 8) {
        float v = src[n * Tt + lane];
        s += v;
        q = fmaf(v, v, q);
    }
    __shared__ float sh[8][64];
    sh[w][lane] = s;
    sh[w][32 + lane] = q;
    __syncthreads();
    if (w == 0) {
        float ss = 0.f, qq = 0.f;
#pragma unroll
        for (int i = 0; i < 8; i++) { ss += sh[i][lane]; qq += sh[i][32 + lane]; }
        g_part[blockIdx.x * 64 + lane] = ss;
        g_part[blockIdx.x * 64 + 32 + lane] = qq;
    }
}

__global__ __launch_bounds__(32) void stats_fin_k(const float* __restrict__ alpha) {
    int t = threadIdx.x;
    if (t >= Tt) return;
    float s = 0.f, q = 0.f;
    for (int b = 0; b < GSTAT; b++) {
        s += g_part[b * 64 + t];
        q += g_part[b * 64 + 32 + t];
    }
    float m = s / (float)Nv;
    float a = alpha[t];
    // ||x - a*m||^2 = q - 2am*(N*m) + N*(a*m)^2 = q + N*m^2*(a^2 - 2a)
    float nsq = q + (float)Nv * m * m * (a * a - 2.f * a);
    g_mean[t] = a * m;
    g_invn[t] = sqrtf((float)Nv) * rsqrtf(nsq);
}

// ---------------- per-layer: normalize + per-node conv/max ----------------
// warp per node, lane = temporal index t
__global__ __launch_bounds__(256) void normconv_k(const float* __restrict__ x, int use_gx,
                           const float* __restrict__ Wc,  // [C*K] this layer
                           const float* __restrict__ bc,  // [C]
                           const float* __restrict__ scale,
                           const float* __restrict__ shift) {
    const float* __restrict__ src = use_gx ? (const float*)g_x : x;
    int lane = threadIdx.x & 31;
    int node = (blockIdx.x * blockDim.x + threadIdx.x) >> 5;
    if (node >= Nv) return;

    float v = src[node * Tt + lane];
    v = fmaf((v - g_mean[lane]) * g_invn[lane], scale[lane], shift[lane]);
    g_xn[node * Tt + lane] = v;

    float win[Kk];
#pragma unroll
    for (int d = -PADc; d <= PADc; d++) {
        int si = lane + d;
        float u = __shfl_sync(0xffffffffu, v, si & 31);
        win[d + PADc] = (si >= 0 && si < Tt) ? u : 0.f;
    }

    float mx = -3.0e38f;
#pragma unroll
    for (int c = 0; c < Cc; c++) {
        float a = bc[c];
#pragma unroll
        for (int k = 0; k < Kk; k++) a = fmaf(win[k], Wc[c * Kk + k], a);
        mx = fmaxf(mx, a);
    }
    g_cm[node * Tt + lane] = mx;
}

// ---------------- per-layer: gather-aggregate + update + ReLU -------------
// warp per node, lane = temporal index t; neighbor ids broadcast via shfl
__global__ __launch_bounds__(256) void aggr_k() {
    int lane = threadIdx.x & 31;
    int node = (blockIdx.x * blockDim.x + threadIdx.x) >> 5;
    if (node >= Nv) return;

    int beg = g_row[node];
    int end = g_row[node + 1];
    float acc = 0.f;
    for (int i = beg; i < end; i += 32) {
        int id = (i + lane < end) ? g_adj[i + lane] : 0;
        int m = end - i;
        if (m > 32) m = 32;
        for (int j = 0; j < m; j++) {
            int s = __shfl_sync(0xffffffffu, id, j);
            acc += g_cm[s * Tt + lane];
        }
    }
    float aggr = acc * g_invdeg[node];
    float v = 0.5f * (g_xn[node * Tt + lane] + aggr);
    g_x[node * Tt + lane] = fmaxf(v, 0.f);
}

// ---------------- output head: out = Wout @ rowsum(x) + bout --------------
__global__ __launch_bounds__(256) void outpart_k(const float* __restrict__ Wout) {
    int tid = threadIdx.x;
    float p0 = 0.f, p1 = 0.f, p2 = 0.f;
    for (int n = blockIdx.x * blockDim.x + tid; n < Nv; n += GOUT * 256) {
        const float4* r = (const float4*)(g_x + n * Tt);
        float s = 0.f;
#pragma unroll
        for (int i = 0; i < 8; i++) {
            float4 f = r[i];
            s += (f.x + f.y) + (f.z + f.w);
        }
        p0 = fmaf(Wout[n], s, p0);
        p1 = fmaf(Wout[Nv + n], s, p1);
        p2 = fmaf(Wout[2 * Nv + n], s, p2);
    }
    __shared__ float sh0[256], sh1[256], sh2[256];
    sh0[tid] = p0; sh1[tid] = p1; sh2[tid] = p2;
    __syncthreads();
    for (int off = 128; off > 0; off >>= 1) {
        if (tid < off) {
            sh0[tid] += sh0[tid + off];
            sh1[tid] += sh1[tid + off];
            sh2[tid] += sh2[tid + off];
        }
        __syncthreads();
    }
    if (tid == 0) {
        g_opart[blockIdx.x * 3 + 0] = sh0[0];
        g_opart[blockIdx.x * 3 + 1] = sh1[0];
        g_opart[blockIdx.x * 3 + 2] = sh2[0];
    }
}

__global__ __launch_bounds__(32) void outfin_k(const float* __restrict__ bout,
                                               float* __restrict__ out) {
    int j = threadIdx.x;
    if (j < 3) {
        float s = bout[j];
        for (int b = 0; b < GOUT; b++) s += g_opart[b * 3 + j];
        out[j] = s;
    }
}

// ---------------- launch ---------------------------------------------------
extern "C" void kernel_launch(void* const* d_in, const int* in_sizes, int n_in,
                              void* d_out, int out_size) {
    const float* x     = (const float*)d_in[0];  // [N,T]
    const float* convW = (const float*)d_in[1];  // [L,C,1,K]
    const float* convb = (const float*)d_in[2];  // [L,C]
    const float* alpha = (const float*)d_in[3];  // [L,T]
    const float* scale = (const float*)d_in[4];  // [L,T]
    const float* shift = (const float*)d_in[5];  // [L,T]
    const float* Wout  = (const float*)d_in[6];  // [3,N]
    const float* bout  = (const float*)d_in[7];  // [3]
    const int*   ei    = (const int*)d_in[8];    // [2,E]
    float* out = (float*)d_out;

    // CSR build (rebuilt every replay: atomics mutate cursor state)
    zero_counts_k<<<(Nv + 255) / 256, 256>>>();
    count_k<<<(Ee + 255) / 256, 256>>>(ei);
    scan_k<<<1, 512>>>();
    scatter_k<<<(Ee + 255) / 256, 256>>>(ei);

    const int nodeBlocks = (Nv + 7) / 8;  // warp per node, 8 warps/block

    for (int l = 0; l < 2; l++) {
        int use_gx = (l > 0) ? 1 : 0;
        stats_k<<<GSTAT, 256>>>(x, use_gx);
        stats_fin_k<<<1, 32>>>(alpha + l * Tt);
        normconv_k<<<nodeBlocks, 256>>>(x, use_gx,
                                        convW + l * Cc * Kk,
                                        convb + l * Cc,
                                        scale + l * Tt,
                                        shift + l * Tt);
        aggr_k<<<nodeBlocks, 256>>>();
    }

    outpart_k<<<GOUT, 256>>>(Wout);
    outfin_k<<<1, 32>>>(bout, out);
}